// round 2
// baseline (speedup 1.0000x reference)
#include <cuda_runtime.h>
#include <cuda_bf16.h>

#define IH 512
#define IW 512
#define OH 256
#define OW 256
#define NBC 128

// Tile: 32x32 outputs per block -> 65x65 input halo.
// Shared arrays split by input-column parity so the 3-tap horizontal gather
// (cols 2ox, 2ox+1, 2ox+2) becomes stride-1 (conflict-free):
//   even cols c=0,2,...,64 -> idx c/2 in [0,32]
//   odd  cols c=1,3,...,63 -> idx c/2 in [0,31]
__global__ __launch_bounds__(256, 4)
void conv_softargmax2d_kernel(const float* __restrict__ x,
                              const float* __restrict__ temp,
                              float* __restrict__ out)
{
    __shared__ float ee[65][34];   // exp, even cols
    __shared__ float eo[65][33];   // exp, odd cols
    __shared__ float pe[65][34];   // exp*x, even cols
    __shared__ float po[65][33];   // exp*x, odd cols

    const int bc  = blockIdx.z;
    const int ox0 = blockIdx.x * 32;
    const int oy0 = blockIdx.y * 32;
    const int xbase = 2 * ox0 - 1;
    const int ybase = 2 * oy0 - 1;

    const float invT = 1.0f / fmaxf(temp[0], 1e-8f);

    const float* __restrict__ xp = x + (size_t)bc * (IH * IW);
    const int tid = threadIdx.y * 32 + threadIdx.x;

    // ---- load + exp phase: 65x65 halo, zero-fill outside image ----
    for (int i = tid; i < 65 * 65; i += 256) {
        int r = i / 65;
        int c = i - r * 65;
        int gy = ybase + r;
        int gx = xbase + c;
        float e = 0.0f, p = 0.0f;
        if ((unsigned)gy < (unsigned)IH && (unsigned)gx < (unsigned)IW) {
            float v = xp[gy * IW + gx];
            e = __expf(v * invT);
            p = e * v;
        }
        int h = c >> 1;
        if (c & 1) { eo[r][h] = e; po[r][h] = p; }
        else       { ee[r][h] = e; pe[r][h] = p; }
    }
    __syncthreads();

    // ---- compute phase: each thread does 4 outputs (fixed ox, oy stride 8) ----
    const int ox = threadIdx.x;
    float* __restrict__ coords = out + (size_t)bc * (2 * OH * OW);
    float* __restrict__ resp   = out + (size_t)NBC * (2 * OH * OW) + (size_t)bc * (OH * OW);

    const float nx = 2.0f / (float)(IW - 1);
    const float ny = 2.0f / (float)(IH - 1);

    #pragma unroll
    for (int oyi = 0; oyi < 4; oyi++) {
        int oy = threadIdx.y + 8 * oyi;
        int rb = 2 * oy;

        float S = 0.0f, V = 0.0f, Sx = 0.0f;
        float rs0 = 0.0f, rs2 = 0.0f;
        #pragma unroll
        for (int dy = 0; dy < 3; dy++) {
            int r = rb + dy;
            float a  = ee[r][ox];
            float b  = eo[r][ox];
            float c2 = ee[r][ox + 1];
            float pa = pe[r][ox];
            float pb = po[r][ox];
            float pc = pe[r][ox + 1];
            float rs = a + b + c2;
            S  += rs;
            V  += pa + pb + pc;
            Sx += c2 - a;
            if (dy == 0) rs0 = rs;
            if (dy == 2) rs2 = rs;
        }
        float Sy   = rs2 - rs0;
        float den  = S + 1e-12f;
        float rinv = 1.0f / den;

        float gxc = (float)(2 * (ox0 + ox));
        float gyc = (float)(2 * (oy0 + oy));

        float cx = fmaf(Sx * rinv + gxc, nx, -1.0f);
        float cy = fmaf(Sy * rinv + gyc, ny, -1.0f);
        float rv = V * rinv;

        int o = (oy0 + oy) * OW + (ox0 + ox);
        coords[o]           = cx;   // channel 0: x
        coords[OH * OW + o] = cy;   // channel 1: y
        resp[o]             = rv;
    }
}

extern "C" void kernel_launch(void* const* d_in, const int* in_sizes, int n_in,
                              void* d_out, int out_size)
{
    // metadata order: x (33554432 elems), temperature (1 elem). Be defensive.
    const float* x = (const float*)d_in[0];
    const float* t = (const float*)d_in[1];
    if (n_in >= 2 && in_sizes[0] == 1) { x = (const float*)d_in[1]; t = (const float*)d_in[0]; }

    dim3 block(32, 8);
    dim3 grid(OW / 32, OH / 32, NBC);
    conv_softargmax2d_kernel<<<grid, block>>>(x, t, (float*)d_out);
}

// round 3
// speedup vs baseline: 3.4029x; 3.4029x over previous
#include <cuda_runtime.h>
#include <cuda_bf16.h>

#define IH 512
#define IW 512
#define OH 256
#define OW 256
#define NBC 128
#define SEG 32            // output rows per block
#define NSEG (OH / SEG)   // 8

// Warp-per-column-strip, registers-only softargmax pool.
// Window for output (oy,ox): input rows 2oy-1..2oy+1, cols 2ox-1..2ox+1.
// Each lane loads {x[r][2ox], x[r][2ox+1]}; left tap comes from lane-1 via shfl.
__global__ __launch_bounds__(256)
void conv_softargmax2d_kernel(const float* __restrict__ x,
                              const float* __restrict__ temp,
                              float* __restrict__ out)
{
    const int lane = threadIdx.x & 31;
    const int warp = threadIdx.x >> 5;
    const int bc   = blockIdx.y;
    const int oy0  = blockIdx.x * SEG;
    const int gox  = warp * 32 + lane;          // output column 0..255
    const bool isL0    = (lane == 0);
    const bool hasLeft = (gox > 0);

    const float invT = __fdividef(1.0f, fmaxf(__ldg(temp), 1e-8f));

    const float* __restrict__ xp = x + (size_t)bc * (IH * IW) + 2 * gox;
    float* __restrict__ coordx = out + (size_t)bc * (2 * OH * OW);
    float* __restrict__ coordy = coordx + OH * OW;
    float* __restrict__ resp   = out + (size_t)NBC * (2 * OH * OW)
                                     + (size_t)bc * (OH * OW);

    // horizontal window sums for one input row:
    //   hs = e(-1)+e(0)+e(+1), hv = same with e*x, hx = e(+1)-e(-1)
    auto rowsums = [&](float2 v, float xl, float& hs, float& hv, float& hx) {
        float e1 = __expf(v.x * invT); float p1 = e1 * v.x;
        float e2 = __expf(v.y * invT); float p2 = e2 * v.y;
        float e0 = __shfl_up_sync(0xffffffffu, e2, 1);
        float p0 = __shfl_up_sync(0xffffffffu, p2, 1);
        if (isL0) {
            if (hasLeft) { e0 = __expf(xl * invT); p0 = e0 * xl; }
            else         { e0 = 0.0f;             p0 = 0.0f;    }
        }
        hs = e0 + e1 + e2;
        hv = p0 + p1 + p2;
        hx = e2 - e0;
    };

    // ---- prologue: sums for row 2*oy0-1 (zero-pad if segment starts at top)
    float hs0 = 0.0f, hv0 = 0.0f, hx0 = 0.0f;
    const float* p = xp + (size_t)(2 * oy0) * IW;   // row 2*oy of first iter
    if (oy0 > 0) {
        const float* pp = p - IW;
        float2 v = *(const float2*)pp;
        float xl = (isL0 && hasLeft) ? pp[-1] : 0.0f;
        rowsums(v, xl, hs0, hv0, hx0);
    }

    // preload first iteration's two rows
    float2 v1 = *(const float2*)p;
    float2 v2 = *(const float2*)(p + IW);
    float xl1 = 0.0f, xl2 = 0.0f;
    if (isL0 && hasLeft) { xl1 = p[-1]; xl2 = p[IW - 1]; }

    const float nx = 2.0f / (float)(IW - 1);
    const float ny = 2.0f / (float)(IH - 1);
    const float gxc = 2.0f * (float)gox;
    float gyc = 2.0f * (float)oy0;
    int o = (oy0)*OW + gox;

    #pragma unroll 4
    for (int i = 0; i < SEG; ++i) {
        // prefetch next iteration's rows (clamped on last iter; reads stay in-bounds)
        const float* pn = p + 2 * IW;
        const float* pc = (i + 1 < SEG) ? pn : p;
        float2 w1 = *(const float2*)pc;
        float2 w2 = *(const float2*)(pc + IW);
        float yl1 = 0.0f, yl2 = 0.0f;
        if (isL0 && hasLeft) { yl1 = pc[-1]; yl2 = pc[IW - 1]; }

        float hs1, hv1, hx1, hs2, hv2, hx2;
        rowsums(v1, xl1, hs1, hv1, hx1);
        rowsums(v2, xl2, hs2, hv2, hx2);

        float S  = hs0 + hs1 + hs2;
        float V  = hv0 + hv1 + hv2;
        float Sx = hx0 + hx1 + hx2;
        float Sy = hs2 - hs0;

        float rinv = __fdividef(1.0f, S + 1e-12f);

        coordx[o] = fmaf(fmaf(Sx, rinv, gxc), nx, -1.0f);
        coordy[o] = fmaf(fmaf(Sy, rinv, gyc), ny, -1.0f);
        resp[o]   = V * rinv;

        // roll: this iteration's last row becomes next iteration's first
        hs0 = hs2; hv0 = hv2; hx0 = hx2;
        v1 = w1; v2 = w2; xl1 = yl1; xl2 = yl2;
        p = pn; o += OW; gyc += 2.0f;
    }
}

extern "C" void kernel_launch(void* const* d_in, const int* in_sizes, int n_in,
                              void* d_out, int out_size)
{
    const float* x = (const float*)d_in[0];
    const float* t = (const float*)d_in[1];
    if (n_in >= 2 && in_sizes[0] == 1) { x = (const float*)d_in[1]; t = (const float*)d_in[0]; }

    dim3 block(256);
    dim3 grid(NSEG, NBC);
    conv_softargmax2d_kernel<<<grid, block>>>(x, t, (float*)d_out);
}